// round 13
// baseline (speedup 1.0000x reference)
#include <cuda_runtime.h>
#include <math.h>

// Problem dims
#define SDIM 256
#define BDIM 64
#define EDIM 1024
#define VDIM 5

#define NCTA 128
#define NTHR 256

// ---------------- scratch (device globals; no allocs allowed) ----------------
#define KT_OFF   0
#define VT_OFF   16777216
#define H1_OFF   33554432
#define C1_OFF   (H1_OFF + 65536)
#define H2_OFF   (C1_OFF + 65536)
#define C2_OFF   (H2_OFF + 65536)
#define QP_OFF   (C2_OFF + 65536)
#define WOP_OFF  (QP_OFF + 524288)
#define CTX_OFF  (WOP_OFF + 524288)
#define ATT_OFF  (CTX_OFF + 65536)
#define G1_OFF   (ATT_OFF + 65536)
#define G2_OFF   (G1_OFF + 524288)
#define BUF_TOTAL (G2_OFF + 524288)

__device__ float g_buf[BUF_TOTAL];
__device__ unsigned g_bar_cnt = 0;
__device__ unsigned g_bar_gen = 0;

// smem layout for gemm (floats): Ad 2 stages x 16x132 (dup-A), Ws 2 stages x 16x68
#define AD_STAGE 2112
#define WS_STAGE 1088
#define WS_BASE  (2 * AD_STAGE)
#define SH_FLOATS (WS_BASE + 2 * WS_STAGE)   // 6400 floats = 25.6 KB

// ---------------- f32x2 packed-FMA helpers ----------------
__device__ __forceinline__ void fma2(unsigned long long &d, unsigned long long a, unsigned long long b) {
    asm("fma.rn.f32x2 %0, %1, %2, %0;" : "+l"(d) : "l"(a), "l"(b));
}
__device__ __forceinline__ float2 upk2(unsigned long long v) {
    float lo, hi;
    asm("mov.b64 {%0,%1}, %2;" : "=f"(lo), "=f"(hi) : "l"(v));
    return make_float2(lo, hi);
}
__device__ __forceinline__ float sigf(float x) { return 1.f / (1.f + expf(-x)); }

// ---------------- grid barrier (all 128 CTAs co-resident) ----------------
__device__ __forceinline__ void grid_bar() {
    __threadfence();
    __syncthreads();
    if (threadIdx.x == 0) {
        volatile unsigned* vg = &g_bar_gen;
        unsigned gen = *vg;
        if (atomicAdd(&g_bar_cnt, 1u) == NCTA - 1u) {
            g_bar_cnt = 0u;
            __threadfence();
            *vg = gen + 1u;
        } else {
            while (*vg == gen) { __nanosleep(32); }
        }
    }
    __syncthreads();
}

// ---------------- K/V precompute GEMM (separate launch; fp32 outputs) ----------------
__global__ __launch_bounds__(256) void gemm_kv(const float* __restrict__ cnn,
                                               const float* __restrict__ w_qkv,
                                               const float* __restrict__ b_qkv) {
    __shared__ float As[16 * 68];
    __shared__ float Ws[16 * 68];
    int tid = threadIdx.x;
    int ty = tid >> 4, tx = tid & 15;
    int lr = tid >> 2, lk = (tid & 3) << 2;
    int n0 = blockIdx.x << 6;
    int m0 = blockIdx.y << 6;

    const float* Arow = cnn + (size_t)(m0 + lr) * EDIM + lk;
    const float* Wrow = w_qkv + (size_t)(EDIM + n0 + lr) * EDIM + lk;

    float acc[4][4];
#pragma unroll
    for (int i = 0; i < 4; i++)
#pragma unroll
        for (int j = 0; j < 4; j++) acc[i][j] = 0.f;

    float4 av = *(const float4*)(Arow);
    float4 wv = *(const float4*)(Wrow);
    for (int kt = 0; kt < EDIM; kt += 16) {
        __syncthreads();
        As[(lk)*68+lr]=av.x; As[(lk+1)*68+lr]=av.y; As[(lk+2)*68+lr]=av.z; As[(lk+3)*68+lr]=av.w;
        Ws[(lk)*68+lr]=wv.x; Ws[(lk+1)*68+lr]=wv.y; Ws[(lk+2)*68+lr]=wv.z; Ws[(lk+3)*68+lr]=wv.w;
        __syncthreads();
        if (kt + 16 < EDIM) {
            av = *(const float4*)(Arow + kt + 16);
            wv = *(const float4*)(Wrow + kt + 16);
        }
#pragma unroll
        for (int k = 0; k < 16; k++) {
            float4 a = *(const float4*)&As[k*68 + (ty<<2)];
            float4 w = *(const float4*)&Ws[k*68 + (tx<<2)];
            float ar[4] = {a.x, a.y, a.z, a.w};
            float wr[4] = {w.x, w.y, w.z, w.w};
#pragma unroll
            for (int i = 0; i < 4; i++)
#pragma unroll
                for (int j = 0; j < 4; j++) acc[i][j] = fmaf(ar[i], wr[j], acc[i][j]);
        }
    }
#pragma unroll
    for (int i = 0; i < 4; i++) {
        int mg = m0 + (ty << 2) + i;
        int s = mg >> 6, b = mg & 63;
#pragma unroll
        for (int j = 0; j < 4; j++) {
            int n = n0 + (tx << 2) + j;
            float v = acc[i][j] + b_qkv[EDIM + n];
            if (n < EDIM) {
                int h = n >> 8, d = n & 255;
                g_buf[KT_OFF + (((b << 2) + h) * 256 + d) * 256 + s] = v;   // K: [b,h,d,s]
            } else {
                int n2 = n - EDIM;
                int h = n2 >> 8, d = n2 & 255;
                g_buf[VT_OFF + (((b << 2) + h) * 256 + s) * 256 + d] = v;   // V: [b,h,s,d]
            }
        }
    }
}

// ---------------- per-step GEMM (M=64), dup-A smem, 2-stage pipeline ----------------
// MOV-free inner loop: A stored duplicated (a,a) so ulonglong2 LDS feeds
// fma.rn.f32x2 directly; W loaded as ulonglong2 (w01,w23).
// If sumSeg >= 0, A-tiles of that k-segment are an 8-slice split-K partial
// (slice stride 65536) plus bias sumBias — summed inline during prefetch.
__device__ __noinline__ void gemm64(
    const float* __restrict__ W0, const float* __restrict__ W1, const float* __restrict__ W2,
    int a0, int a1, int a2,
    int ldw0, int ldw1, int ldw2,
    int N, int Kper, int outOff, int bx, int by, float* sh,
    int sumSeg, const float* __restrict__ sumBias)
{
    float* AdB = sh;
    float* WsB = sh + WS_BASE;
    int tid = threadIdx.x;
    int ty = tid >> 4, tx = tid & 15;
    int lr = tid >> 2, lk = (tid & 3) << 2;
    int n0 = bx << 6;
    int k0 = by * Kper;
    int nt = Kper >> 4;

    unsigned long long a00=0,a01=0,a10=0,a11=0,a20=0,a21=0,a30=0,a31=0;

    float4 av, wv;
    // --- prefetch tile 0 ---
    {
        int kk = k0;
        int seg = kk >> 10, kin = kk & 1023;
        int ab = (seg == 0 ? a0 : (seg == 1 ? a1 : a2));
        const float* Wb = (seg == 0 ? W0 : (seg == 1 ? W1 : W2));
        int ldw = (seg == 0 ? ldw0 : (seg == 1 ? ldw1 : ldw2));
        const float* Abase = g_buf + ab + lr * EDIM + kin + lk;
        av = __ldcg((const float4*)Abase);
        if (seg == sumSeg) {
#pragma unroll
            for (int sp = 1; sp < 8; sp++) {
                float4 u = __ldcg((const float4*)(Abase + sp * 65536));
                av.x += u.x; av.y += u.y; av.z += u.z; av.w += u.w;
            }
            av.x += sumBias[kin + lk]; av.y += sumBias[kin + lk + 1];
            av.z += sumBias[kin + lk + 2]; av.w += sumBias[kin + lk + 3];
        }
        wv = __ldg((const float4*)(Wb + (size_t)(n0 + lr) * ldw + kin + lk));
    }
    // store tile 0 -> stage 0
    {
        float* A = AdB; float* W = WsB;
        *(float2*)&A[(lk+0)*132 + lr*2] = make_float2(av.x, av.x);
        *(float2*)&A[(lk+1)*132 + lr*2] = make_float2(av.y, av.y);
        *(float2*)&A[(lk+2)*132 + lr*2] = make_float2(av.z, av.z);
        *(float2*)&A[(lk+3)*132 + lr*2] = make_float2(av.w, av.w);
        W[(lk+0)*68 + lr] = wv.x; W[(lk+1)*68 + lr] = wv.y;
        W[(lk+2)*68 + lr] = wv.z; W[(lk+3)*68 + lr] = wv.w;
    }
    __syncthreads();

    for (int t = 0; t < nt; t++) {
        if (t + 1 < nt) {   // prefetch next tile into regs
            int kk = k0 + ((t + 1) << 4);
            int seg = kk >> 10, kin = kk & 1023;
            int ab = (seg == 0 ? a0 : (seg == 1 ? a1 : a2));
            const float* Wb = (seg == 0 ? W0 : (seg == 1 ? W1 : W2));
            int ldw = (seg == 0 ? ldw0 : (seg == 1 ? ldw1 : ldw2));
            const float* Abase = g_buf + ab + lr * EDIM + kin + lk;
            av = __ldcg((const float4*)Abase);
            if (seg == sumSeg) {
#pragma unroll
                for (int sp = 1; sp < 8; sp++) {
                    float4 u = __ldcg((const float4*)(Abase + sp * 65536));
                    av.x += u.x; av.y += u.y; av.z += u.z; av.w += u.w;
                }
                av.x += sumBias[kin + lk]; av.y += sumBias[kin + lk + 1];
                av.z += sumBias[kin + lk + 2]; av.w += sumBias[kin + lk + 3];
            }
            wv = __ldg((const float4*)(Wb + (size_t)(n0 + lr) * ldw + kin + lk));
        }
        const float* A = AdB + (t & 1) * AD_STAGE;
        const float* W = WsB + (t & 1) * WS_STAGE;
#pragma unroll
        for (int k = 0; k < 16; k++) {
            ulonglong2 aA = *(const ulonglong2*)&A[k*132 + ty*8];      // (a0,a0),(a1,a1)
            ulonglong2 aB = *(const ulonglong2*)&A[k*132 + ty*8 + 4];  // (a2,a2),(a3,a3)
            ulonglong2 w  = *(const ulonglong2*)&W[k*68 + tx*4];       // (w0,w1),(w2,w3)
            fma2(a00, aA.x, w.x); fma2(a01, aA.x, w.y);
            fma2(a10, aA.y, w.x); fma2(a11, aA.y, w.y);
            fma2(a20, aB.x, w.x); fma2(a21, aB.x, w.y);
            fma2(a30, aB.y, w.x); fma2(a31, aB.y, w.y);
        }
        if (t + 1 < nt) {   // store prefetched tile -> other stage
            float* A2 = AdB + ((t + 1) & 1) * AD_STAGE;
            float* W2 = WsB + ((t + 1) & 1) * WS_STAGE;
            *(float2*)&A2[(lk+0)*132 + lr*2] = make_float2(av.x, av.x);
            *(float2*)&A2[(lk+1)*132 + lr*2] = make_float2(av.y, av.y);
            *(float2*)&A2[(lk+2)*132 + lr*2] = make_float2(av.z, av.z);
            *(float2*)&A2[(lk+3)*132 + lr*2] = make_float2(av.w, av.w);
            W2[(lk+0)*68 + lr] = wv.x; W2[(lk+1)*68 + lr] = wv.y;
            W2[(lk+2)*68 + lr] = wv.z; W2[(lk+3)*68 + lr] = wv.w;
        }
        __syncthreads();
    }

    float* op = g_buf + outOff + (size_t)(by << 6) * N + n0 + (tx << 2);
    float2 p0, p1;
    p0 = upk2(a00); p1 = upk2(a01); *(float4*)(op + (size_t)((ty<<2)+0)*N) = make_float4(p0.x,p0.y,p1.x,p1.y);
    p0 = upk2(a10); p1 = upk2(a11); *(float4*)(op + (size_t)((ty<<2)+1)*N) = make_float4(p0.x,p0.y,p1.x,p1.y);
    p0 = upk2(a20); p1 = upk2(a21); *(float4*)(op + (size_t)((ty<<2)+2)*N) = make_float4(p0.x,p0.y,p1.x,p1.y);
    p0 = upk2(a30); p1 = upk2(a31); *(float4*)(op + (size_t)((ty<<2)+3)*N) = make_float4(p0.x,p0.y,p1.x,p1.y);
}

// ---------------- attention: each CTA handles 2 (b,h); fp32 K/V; shuffle softmax ----------------
__device__ __noinline__ void attn_dev(const float* __restrict__ b_qkv, float* sh) {
    float* qs   = sh;          // 256
    float* pr   = sh + 256;    // 256
    float* wred = sh + 512;    // 8
    int t = threadIdx.x;
    int lane = t & 31, w = t >> 5;
#pragma unroll 1
    for (int i = 0; i < 2; i++) {
        int bh = (blockIdx.x << 1) + i;   // 0..255
        int b = bh >> 2, h = bh & 3;
        int e = (h << 8) + t;
        float qv = b_qkv[e];
#pragma unroll
        for (int sp = 0; sp < 8; sp++) qv += __ldcg(g_buf + QP_OFF + sp * 65536 + (b << 10) + e);
        qs[t] = qv * 0.0625f;             // fold 1/sqrt(256)
        __syncthreads();

        const float* Kb = g_buf + KT_OFF + bh * 65536;
        float acc = 0.f;
#pragma unroll 8
        for (int d = 0; d < 256; d++) acc += qs[d] * Kb[(d << 8) + t];

        float m = acc;
#pragma unroll
        for (int off = 16; off; off >>= 1) m = fmaxf(m, __shfl_xor_sync(0xffffffffu, m, off));
        if (lane == 0) wred[w] = m;
        __syncthreads();
        float mx = wred[0];
#pragma unroll
        for (int j = 1; j < 8; j++) mx = fmaxf(mx, wred[j]);
        float ex = expf(acc - mx);
        float s = ex;
#pragma unroll
        for (int off = 16; off; off >>= 1) s += __shfl_xor_sync(0xffffffffu, s, off);
        __syncthreads();                  // protect wred reuse
        if (lane == 0) wred[w] = s;
        __syncthreads();
        float tot = wred[0];
#pragma unroll
        for (int j = 1; j < 8; j++) tot += wred[j];
        pr[t] = ex * (1.f / tot);
        __syncthreads();

        const float* Vb = g_buf + VT_OFF + bh * 65536;
        float c = 0.f;
#pragma unroll 8
        for (int s2 = 0; s2 < 256; s2++) c += pr[s2] * Vb[(s2 << 8) + t];
        g_buf[ATT_OFF + (b << 10) + e] = c;
        __syncthreads();                  // before next i overwrites qs
    }
}

// ---------------- LSTM cell: sums 2 split-K gate partials + biases ----------------
__device__ __noinline__ void cell_dev(int gOff, const float* __restrict__ bi, const float* __restrict__ bh,
                                      int hOff, int cOff) {
    for (int idx = blockIdx.x * NTHR + threadIdx.x; idx < 65536; idx += NCTA * NTHR) {
        int b = idx >> 10, e = idx & 1023;
        const float* g0 = g_buf + gOff + (size_t)b * 4096;
        const float* g1 = g_buf + gOff + (size_t)(64 + b) * 4096;
        float gi = __ldcg(g0 + e)        + __ldcg(g1 + e)        + bi[e]        + bh[e];
        float gf = __ldcg(g0 + 1024 + e) + __ldcg(g1 + 1024 + e) + bi[1024 + e] + bh[1024 + e];
        float gg = __ldcg(g0 + 2048 + e) + __ldcg(g1 + 2048 + e) + bi[2048 + e] + bh[2048 + e];
        float go = __ldcg(g0 + 3072 + e) + __ldcg(g1 + 3072 + e) + bi[3072 + e] + bh[3072 + e];
        float c = __ldcg(g_buf + cOff + idx);
        float cn = sigf(gf) * c + sigf(gi) * tanhf(gg);
        g_buf[cOff + idx] = cn;
        g_buf[hOff + idx] = sigf(go) * tanhf(cn);
    }
}

// ---------------- output head (CTAs 0..63, 5 warps used) ----------------
__device__ __forceinline__ void head_dev(const float* __restrict__ w_out, const float* __restrict__ b_out,
                                         float* __restrict__ out, int t) {
    if (blockIdx.x < 64 && threadIdx.x < 160) {
        int b = blockIdx.x;
        int w = threadIdx.x >> 5, lane = threadIdx.x & 31;
        const float* hb = g_buf + H2_OFF + (b << 10);
        const float* wr = w_out + w * 1024;
        float a = 0.f;
        for (int j = lane; j < 1024; j += 32) a += __ldcg(hb + j) * wr[j];
#pragma unroll
        for (int off = 16; off; off >>= 1) a += __shfl_down_sync(0xffffffffu, a, off);
        if (lane == 0) {
            a += b_out[w];
            if (w >= 2) a = 1.f / (1.f + expf(-a));
            out[((t << 6) + b) * VDIM + w] = a;
        }
    }
}

// ---------------- persistent main kernel: whole 256-step recurrence ----------------
__global__ __launch_bounds__(NTHR, 1) void main_kernel(
    const float* __restrict__ w_qkv, const float* __restrict__ b_qkv,
    const float* __restrict__ w_o,   const float* __restrict__ b_o,
    const float* __restrict__ w_ih1, const float* __restrict__ w_hh1,
    const float* __restrict__ b_ih1, const float* __restrict__ b_hh1,
    const float* __restrict__ w_ih2, const float* __restrict__ w_hh2,
    const float* __restrict__ b_ih2, const float* __restrict__ b_hh2,
    const float* __restrict__ w_out, const float* __restrict__ b_out,
    float* __restrict__ out)
{
    __shared__ __align__(16) float sh[SH_FLOATS];
    int r = blockIdx.x;

    // zero recurrent state (h1,c1,h2,c2)
    for (int i = r * NTHR + threadIdx.x; i < 4 * BDIM * EDIM; i += NCTA * NTHR)
        g_buf[H1_OFF + i] = 0.f;
    grid_bar();

    for (int t = 0; t < SDIM; t++) {
        // phase 1: head for t-1 overlapped with q projection (both read finalized h2)
        if (t > 0) head_dev(w_out, b_out, out, t - 1);
        gemm64(w_qkv, w_qkv, w_qkv, H2_OFF, H2_OFF, H2_OFF,
               EDIM, EDIM, EDIM, EDIM, 128, QP_OFF, r & 15, r >> 4, sh, -1, 0);
        grid_bar();
        // phase 2: attention (sums q partials + b_q)
        attn_dev(b_qkv, sh);
        grid_bar();
        // phase 3: ctx partials = att @ w_o^T (8-way split-K, consumed inline by g1)
        gemm64(w_o, w_o, w_o, ATT_OFF, ATT_OFF, ATT_OFF,
               EDIM, EDIM, EDIM, EDIM, 128, WOP_OFF, r & 15, r >> 4, sh, -1, 0);
        grid_bar();
        // phase 4: gates1 = h2@Wih1[:,:E]^T + ctx@Wih1[:,E:]^T + h1@Whh1^T
        //          (ctx = 8 WOP slices + b_o summed inline in the A-prefetch)
        gemm64(w_ih1, w_ih1 + 1024, w_hh1, H2_OFF, WOP_OFF, H1_OFF,
               2048, 2048, 1024, 4096, 1536, G1_OFF, r >> 1, r & 1, sh, 1, b_o);
        grid_bar();
        // phase 5: LSTM cell 1
        cell_dev(G1_OFF, b_ih1, b_hh1, H1_OFF, C1_OFF);
        grid_bar();
        // phase 6: gates2 = h1new@Wih2^T + h2prev@Whh2^T
        gemm64(w_ih2, w_hh2, w_hh2, H1_OFF, H2_OFF, H2_OFF,
               1024, 1024, 1024, 4096, 1024, G2_OFF, r >> 1, r & 1, sh, -1, 0);
        grid_bar();
        // phase 7: LSTM cell 2 (writes new h2)
        cell_dev(G2_OFF, b_ih2, b_hh2, H2_OFF, C2_OFF);
        grid_bar();
    }
    head_dev(w_out, b_out, out, SDIM - 1);
}

// ---------------- host ----------------
extern "C" void kernel_launch(void* const* d_in, const int* in_sizes, int n_in,
                              void* d_out, int out_size) {
    const float* cnn    = (const float*)d_in[0];
    const float* w_qkv  = (const float*)d_in[1];
    const float* b_qkv  = (const float*)d_in[2];
    const float* w_o    = (const float*)d_in[3];
    const float* b_o    = (const float*)d_in[4];
    const float* w_ih1  = (const float*)d_in[5];
    const float* w_hh1  = (const float*)d_in[6];
    const float* b_ih1  = (const float*)d_in[7];
    const float* b_hh1  = (const float*)d_in[8];
    const float* w_ih2  = (const float*)d_in[9];
    const float* w_hh2  = (const float*)d_in[10];
    const float* b_ih2  = (const float*)d_in[11];
    const float* b_hh2  = (const float*)d_in[12];
    const float* w_out  = (const float*)d_in[13];
    const float* b_out  = (const float*)d_in[14];
    float* out = (float*)d_out;

    // K/V projections (fp32) into attention-friendly layouts
    gemm_kv<<<dim3(32, 256), 256>>>(cnn, w_qkv, b_qkv);

    // entire recurrence in one persistent kernel (128 co-resident CTAs)
    main_kernel<<<NCTA, NTHR>>>(w_qkv, b_qkv, w_o, b_o,
                                w_ih1, w_hh1, b_ih1, b_hh1,
                                w_ih2, w_hh2, b_ih2, b_hh2,
                                w_out, b_out, out);
}

// round 14
// speedup vs baseline: 1.5026x; 1.5026x over previous
#include <cuda_runtime.h>
#include <math.h>

// Problem dims
#define SDIM 256
#define BDIM 64
#define EDIM 1024
#define VDIM 5

#define NCTA 256
#define NTHR 256

// ---------------- scratch (device globals; no allocs allowed) ----------------
#define KT_OFF   0
#define VT_OFF   16777216
#define H1_OFF   33554432
#define C1_OFF   (H1_OFF + 65536)
#define H2_OFF   (C1_OFF + 65536)
#define C2_OFF   (H2_OFF + 65536)
#define QP_OFF   (C2_OFF + 65536)              // 16 x 65536 split-K q partials
#define WOP_OFF  (QP_OFF + 16*65536)           // 16 x 65536 split-K wo partials
#define CTX_OFF  (WOP_OFF + 16*65536)
#define ATT_OFF  (CTX_OFF + 65536)
#define G1_OFF   (ATT_OFF + 65536)             // 4 x 262144 gate1 partials
#define G2_OFF   (G1_OFF + 4*262144)           // 4 x 262144 gate2 partials
#define QT_OFF   (G2_OFF + 4*262144)           // w_q  k-major [1024 x 1024]
#define OT_OFF   (QT_OFF + 1048576)            // w_o  k-major [1024 x 1024]
#define G1T_OFF  (OT_OFF + 1048576)            // gates1 k-major [3072 x 4096]
#define G2T_OFF  (G1T_OFF + 3072*4096)         // gates2 k-major [2048 x 4096]
#define BUF_TOTAL (G2T_OFF + 2048*4096)

__device__ float g_buf[BUF_TOTAL];
__device__ unsigned g_bar_cnt = 0;
__device__ unsigned g_bar_gen = 0;

// smem: A dup 2 stages x 16x132, W 4 stages x 16x64
#define AD_STAGE 2112
#define WS_STAGE 1024
#define SH_FLOATS (2*AD_STAGE + 4*WS_STAGE)    // 8320 floats = 33.3 KB

// ---------------- helpers ----------------
__device__ __forceinline__ void fma2(unsigned long long &d, unsigned long long a, unsigned long long b) {
    asm("fma.rn.f32x2 %0, %1, %2, %0;" : "+l"(d) : "l"(a), "l"(b));
}
__device__ __forceinline__ float2 upk2(unsigned long long v) {
    float lo, hi;
    asm("mov.b64 {%0,%1}, %2;" : "=f"(lo), "=f"(hi) : "l"(v));
    return make_float2(lo, hi);
}
__device__ __forceinline__ float sigf(float x) { return 1.f / (1.f + expf(-x)); }
__device__ __forceinline__ void cp16(float* dst_smem, const float* src) {
    unsigned d = (unsigned)__cvta_generic_to_shared(dst_smem);
    asm volatile("cp.async.cg.shared.global [%0], [%1], 16;" :: "r"(d), "l"(src));
}
#define CP_COMMIT() asm volatile("cp.async.commit_group;" ::: "memory")
#define CP_WAIT2()  asm volatile("cp.async.wait_group 2;" ::: "memory")

// ---------------- grid barrier (all 256 CTAs co-resident) ----------------
__device__ __forceinline__ void grid_bar() {
    __threadfence();
    __syncthreads();
    if (threadIdx.x == 0) {
        volatile unsigned* vg = &g_bar_gen;
        unsigned gen = *vg;
        if (atomicAdd(&g_bar_cnt, 1u) == NCTA - 1u) {
            g_bar_cnt = 0u;
            __threadfence();
            *vg = gen + 1u;
        } else {
            while (*vg == gen) { __nanosleep(32); }
        }
    }
    __syncthreads();
}

// ---------------- one-time weight transpose to k-major ----------------
// dst(g_buf+dstOff)[(kdst0+k)*ldd + n] = src[n*lds + k]
__global__ void trans_tiled(const float* __restrict__ src, int lds,
                            int dstOff, int ldd, int kdst0) {
    __shared__ float tile[32][33];
    int kb = blockIdx.x << 5, nb = blockIdx.y << 5;
    int tx = threadIdx.x, ty = threadIdx.y;   // 32 x 8
#pragma unroll
    for (int j = 0; j < 4; j++)
        tile[ty + j*8][tx] = src[(size_t)(nb + ty + j*8) * lds + kb + tx];
    __syncthreads();
    float* dst = g_buf + dstOff;
#pragma unroll
    for (int j = 0; j < 4; j++)
        dst[(size_t)(kdst0 + kb + ty + j*8) * ldd + nb + tx] = tile[tx][ty + j*8];
}

// ---------------- K/V precompute GEMM (separate launch; fp32 outputs) ----------------
__global__ __launch_bounds__(256) void gemm_kv(const float* __restrict__ cnn,
                                               const float* __restrict__ w_qkv,
                                               const float* __restrict__ b_qkv) {
    __shared__ float As[16 * 68];
    __shared__ float Ws[16 * 68];
    int tid = threadIdx.x;
    int ty = tid >> 4, tx = tid & 15;
    int lr = tid >> 2, lk = (tid & 3) << 2;
    int n0 = blockIdx.x << 6;
    int m0 = blockIdx.y << 6;

    const float* Arow = cnn + (size_t)(m0 + lr) * EDIM + lk;
    const float* Wrow = w_qkv + (size_t)(EDIM + n0 + lr) * EDIM + lk;

    float acc[4][4];
#pragma unroll
    for (int i = 0; i < 4; i++)
#pragma unroll
        for (int j = 0; j < 4; j++) acc[i][j] = 0.f;

    float4 av = *(const float4*)(Arow);
    float4 wv = *(const float4*)(Wrow);
    for (int kt = 0; kt < EDIM; kt += 16) {
        __syncthreads();
        As[(lk)*68+lr]=av.x; As[(lk+1)*68+lr]=av.y; As[(lk+2)*68+lr]=av.z; As[(lk+3)*68+lr]=av.w;
        Ws[(lk)*68+lr]=wv.x; Ws[(lk+1)*68+lr]=wv.y; Ws[(lk+2)*68+lr]=wv.z; Ws[(lk+3)*68+lr]=wv.w;
        __syncthreads();
        if (kt + 16 < EDIM) {
            av = *(const float4*)(Arow + kt + 16);
            wv = *(const float4*)(Wrow + kt + 16);
        }
#pragma unroll
        for (int k = 0; k < 16; k++) {
            float4 a = *(const float4*)&As[k*68 + (ty<<2)];
            float4 w = *(const float4*)&Ws[k*68 + (tx<<2)];
            float ar[4] = {a.x, a.y, a.z, a.w};
            float wr[4] = {w.x, w.y, w.z, w.w};
#pragma unroll
            for (int i = 0; i < 4; i++)
#pragma unroll
                for (int j = 0; j < 4; j++) acc[i][j] = fmaf(ar[i], wr[j], acc[i][j]);
        }
    }
#pragma unroll
    for (int i = 0; i < 4; i++) {
        int mg = m0 + (ty << 2) + i;
        int s = mg >> 6, b = mg & 63;
#pragma unroll
        for (int j = 0; j < 4; j++) {
            int n = n0 + (tx << 2) + j;
            float v = acc[i][j] + b_qkv[EDIM + n];
            if (n < EDIM) {
                int h = n >> 8, d = n & 255;
                g_buf[KT_OFF + (((b << 2) + h) * 256 + d) * 256 + s] = v;   // K: [b,h,d,s]
            } else {
                int n2 = n - EDIM;
                int h = n2 >> 8, d = n2 & 255;
                g_buf[VT_OFF + (((b << 2) + h) * 256 + s) * 256 + d] = v;   // V: [b,h,s,d]
            }
        }
    }
}

// ---------------- per-step GEMM (M=64): k-major W via 4-stage cp.async ----------------
// WT[k*N + n] pre-transposed. A comes from g_buf with per-1024-k segment offsets.
__device__ __noinline__ void gemm64(const float* __restrict__ WT, int N,
                                    int a0, int a1, int a2,
                                    int Kper, int outOff, int bx, int by,
                                    float* shA, float* shW)
{
    int tid = threadIdx.x;
    int ty = tid >> 4, tx = tid & 15;
    int lr = tid >> 2, lk = (tid & 3) << 2;      // A loader: row lr, k-quarter lk
    int kk = tid >> 4, nq = tid & 15;            // W loader: k-row kk, n-quarter nq
    int n0 = bx << 6;
    int k0 = by * Kper;
    int nt = Kper >> 4;

    const float* wsrc = WT + (size_t)(k0 + kk) * N + n0 + (nq << 2);
    float* wdst = shW + kk * 64 + (nq << 2);

    unsigned long long a00=0,a01=0,a10=0,a11=0,a20=0,a21=0,a30=0,a31=0;

    // ---- preamble: issue W stages 0..2, stage A(0), prefetch A(1) ----
#pragma unroll
    for (int s = 0; s < 3; s++) {
        if (s < nt) cp16(wdst + (s & 3) * WS_STAGE, wsrc + (size_t)(s << 4) * N);
        CP_COMMIT();
    }
    float4 av;
    {
        int seg = k0 >> 10, kin = k0 & 1023;
        int ab = (seg == 0 ? a0 : (seg == 1 ? a1 : a2));
        av = __ldcg((const float4*)(g_buf + ab + lr * 1024 + kin + lk));
        float* A = shA;
        *(float2*)&A[(lk+0)*132 + lr*2] = make_float2(av.x, av.x);
        *(float2*)&A[(lk+1)*132 + lr*2] = make_float2(av.y, av.y);
        *(float2*)&A[(lk+2)*132 + lr*2] = make_float2(av.z, av.z);
        *(float2*)&A[(lk+3)*132 + lr*2] = make_float2(av.w, av.w);
    }
    if (nt > 1) {
        int kn = k0 + 16;
        int seg = kn >> 10, kin = kn & 1023;
        int ab = (seg == 0 ? a0 : (seg == 1 ? a1 : a2));
        av = __ldcg((const float4*)(g_buf + ab + lr * 1024 + kin + lk));
    }
    CP_WAIT2();
    __syncthreads();

    // ---- main loop: one commit + one sync per tile ----
    for (int t = 0; t < nt; t++) {
        if (t + 3 < nt) cp16(wdst + ((t + 3) & 3) * WS_STAGE, wsrc + (size_t)((t + 3) << 4) * N);
        CP_COMMIT();
        if (t + 1 < nt) {   // stage A(t+1)
            float* A = shA + ((t + 1) & 1) * AD_STAGE;
            *(float2*)&A[(lk+0)*132 + lr*2] = make_float2(av.x, av.x);
            *(float2*)&A[(lk+1)*132 + lr*2] = make_float2(av.y, av.y);
            *(float2*)&A[(lk+2)*132 + lr*2] = make_float2(av.z, av.z);
            *(float2*)&A[(lk+3)*132 + lr*2] = make_float2(av.w, av.w);
        }
        if (t + 2 < nt) {   // prefetch A(t+2)
            int kn = k0 + ((t + 2) << 4);
            int seg = kn >> 10, kin = kn & 1023;
            int ab = (seg == 0 ? a0 : (seg == 1 ? a1 : a2));
            av = __ldcg((const float4*)(g_buf + ab + lr * 1024 + kin + lk));
        }
        const float* A = shA + (t & 1) * AD_STAGE;
        const float* W = shW + (t & 3) * WS_STAGE;
#pragma unroll
        for (int k = 0; k < 16; k++) {
            ulonglong2 aA = *(const ulonglong2*)&A[k*132 + ty*8];      // (a0,a0),(a1,a1)
            ulonglong2 aB = *(const ulonglong2*)&A[k*132 + ty*8 + 4];  // (a2,a2),(a3,a3)
            ulonglong2 w  = *(const ulonglong2*)&W[k*64 + tx*4];       // (w0,w1),(w2,w3)
            fma2(a00, aA.x, w.x); fma2(a01, aA.x, w.y);
            fma2(a10, aA.y, w.x); fma2(a11, aA.y, w.y);
            fma2(a20, aB.x, w.x); fma2(a21, aB.x, w.y);
            fma2(a30, aB.y, w.x); fma2(a31, aB.y, w.y);
        }
        CP_WAIT2();
        __syncthreads();
    }

    float* op = g_buf + outOff + (size_t)(by << 6) * N + n0 + (tx << 2);
    float2 p0, p1;
    p0 = upk2(a00); p1 = upk2(a01); *(float4*)(op + (size_t)((ty<<2)+0)*N) = make_float4(p0.x,p0.y,p1.x,p1.y);
    p0 = upk2(a10); p1 = upk2(a11); *(float4*)(op + (size_t)((ty<<2)+1)*N) = make_float4(p0.x,p0.y,p1.x,p1.y);
    p0 = upk2(a20); p1 = upk2(a21); *(float4*)(op + (size_t)((ty<<2)+2)*N) = make_float4(p0.x,p0.y,p1.x,p1.y);
    p0 = upk2(a30); p1 = upk2(a31); *(float4*)(op + (size_t)((ty<<2)+3)*N) = make_float4(p0.x,p0.y,p1.x,p1.y);
}

// ---------------- attention: one (b,h) per CTA; fp32 K/V; shuffle softmax ----------------
__device__ __noinline__ void attn_dev(const float* __restrict__ b_qkv, float* sh) {
    float* qs   = sh;          // 256
    float* pr   = sh + 256;    // 256
    float* wred = sh + 512;    // 8
    int t = threadIdx.x;
    int lane = t & 31, w = t >> 5;
    int bh = blockIdx.x;              // 0..255
    int b = bh >> 2, h = bh & 3;
    int e = (h << 8) + t;
    float qv = b_qkv[e];
#pragma unroll
    for (int sp = 0; sp < 16; sp++) qv += __ldcg(g_buf + QP_OFF + sp * 65536 + (b << 10) + e);
    qs[t] = qv * 0.0625f;             // fold 1/sqrt(256)
    __syncthreads();

    const float* Kb = g_buf + KT_OFF + bh * 65536;
    float acc = 0.f;
#pragma unroll 16
    for (int d = 0; d < 256; d++) acc += qs[d] * Kb[(d << 8) + t];

    float m = acc;
#pragma unroll
    for (int off = 16; off; off >>= 1) m = fmaxf(m, __shfl_xor_sync(0xffffffffu, m, off));
    if (lane == 0) wred[w] = m;
    __syncthreads();
    float mx = wred[0];
#pragma unroll
    for (int j = 1; j < 8; j++) mx = fmaxf(mx, wred[j]);
    float ex = expf(acc - mx);
    float s = ex;
#pragma unroll
    for (int off = 16; off; off >>= 1) s += __shfl_xor_sync(0xffffffffu, s, off);
    __syncthreads();
    if (lane == 0) wred[w] = s;
    __syncthreads();
    float tot = wred[0];
#pragma unroll
    for (int j = 1; j < 8; j++) tot += wred[j];
    pr[t] = ex * (1.f / tot);
    __syncthreads();

    const float* Vb = g_buf + VT_OFF + bh * 65536;
    float c = 0.f;
#pragma unroll 16
    for (int s2 = 0; s2 < 256; s2++) c += pr[s2] * Vb[(s2 << 8) + t];
    g_buf[ATT_OFF + (b << 10) + e] = c;
}

// ---------------- w_o split-K reduce + bias (16 slices) ----------------
__device__ __forceinline__ void wored_dev(const float* __restrict__ b_o) {
    int idx = blockIdx.x * NTHR + threadIdx.x;    // exactly 65536
    int e = idx & 1023;
    float v = b_o[e];
#pragma unroll
    for (int sp = 0; sp < 16; sp++) v += __ldcg(g_buf + WOP_OFF + sp * 65536 + idx);
    g_buf[CTX_OFF + idx] = v;
}

// ---------------- LSTM cell: sums 4 split-K gate partials + biases ----------------
__device__ __noinline__ void cell_dev(int gOff, const float* __restrict__ bi, const float* __restrict__ bh,
                                      int hOff, int cOff) {
    int idx = blockIdx.x * NTHR + threadIdx.x;    // exactly 65536 = (b,e)
    int b = idx >> 10, e = idx & 1023;
    const float* gb = g_buf + gOff + (size_t)b * 4096;
    float gi = bi[e]        + bh[e];
    float gf = bi[1024 + e] + bh[1024 + e];
    float gg = bi[2048 + e] + bh[2048 + e];
    float go = bi[3072 + e] + bh[3072 + e];
#pragma unroll
    for (int sp = 0; sp < 4; sp++) {
        const float* g = gb + sp * 262144;
        gi += __ldcg(g + e);
        gf += __ldcg(g + 1024 + e);
        gg += __ldcg(g + 2048 + e);
        go += __ldcg(g + 3072 + e);
    }
    float c = __ldcg(g_buf + cOff + idx);
    float cn = sigf(gf) * c + sigf(gi) * tanhf(gg);
    g_buf[cOff + idx] = cn;
    g_buf[hOff + idx] = sigf(go) * tanhf(cn);
}

// ---------------- output head (CTAs 0..63, 5 warps used) ----------------
__device__ __forceinline__ void head_dev(const float* __restrict__ w_out, const float* __restrict__ b_out,
                                         float* __restrict__ out, int t) {
    if (blockIdx.x < 64 && threadIdx.x < 160) {
        int b = blockIdx.x;
        int w = threadIdx.x >> 5, lane = threadIdx.x & 31;
        const float* hb = g_buf + H2_OFF + (b << 10);
        const float* wr = w_out + w * 1024;
        float a = 0.f;
        for (int j = lane; j < 1024; j += 32) a += __ldcg(hb + j) * wr[j];
#pragma unroll
        for (int off = 16; off; off >>= 1) a += __shfl_down_sync(0xffffffffu, a, off);
        if (lane == 0) {
            a += b_out[w];
            if (w >= 2) a = 1.f / (1.f + expf(-a));
            out[((t << 6) + b) * VDIM + w] = a;
        }
    }
}

// ---------------- persistent main kernel: whole 256-step recurrence ----------------
__global__ void __launch_bounds__(NTHR, 2) main_kernel(
    const float* __restrict__ b_qkv, const float* __restrict__ b_o,
    const float* __restrict__ b_ih1, const float* __restrict__ b_hh1,
    const float* __restrict__ b_ih2, const float* __restrict__ b_hh2,
    const float* __restrict__ w_out, const float* __restrict__ b_out,
    float* __restrict__ out)
{
    __shared__ __align__(16) float sh[SH_FLOATS];
    float* shA = sh;
    float* shW = sh + 2 * AD_STAGE;
    int r = blockIdx.x;

    // zero recurrent state (h1,c1,h2,c2): 262144 elems over 65536 threads
    for (int i = r * NTHR + threadIdx.x; i < 4 * BDIM * EDIM; i += NCTA * NTHR)
        g_buf[H1_OFF + i] = 0.f;
    grid_bar();

    const float* QT  = g_buf + QT_OFF;
    const float* OT  = g_buf + OT_OFF;
    const float* G1T = g_buf + G1T_OFF;
    const float* G2T = g_buf + G2T_OFF;

    for (int t = 0; t < SDIM; t++) {
        // phase 1: head(t-1) overlapped with q projection (both read finalized h2)
        if (t > 0) head_dev(w_out, b_out, out, t - 1);
        gemm64(QT, 1024, H2_OFF, H2_OFF, H2_OFF, 64, QP_OFF, r & 15, r >> 4, shA, shW);
        grid_bar();
        // phase 2: attention (sums 16 q partials + b_q)
        attn_dev(b_qkv, sh);
        grid_bar();
        // phase 3: wo partials = att @ w_o^T
        gemm64(OT, 1024, ATT_OFF, ATT_OFF, ATT_OFF, 64, WOP_OFF, r & 15, r >> 4, shA, shW);
        grid_bar();
        // phase 4: ctx = sum of 16 partials + b_o
        wored_dev(b_o);
        grid_bar();
        // phase 5: gates1 = [h2|ctx|h1] @ G1T   (K=3072, 4-way split)
        gemm64(G1T, 4096, H2_OFF, CTX_OFF, H1_OFF, 768, G1_OFF, r >> 2, r & 3, shA, shW);
        grid_bar();
        // phase 6: LSTM cell 1
        cell_dev(G1_OFF, b_ih1, b_hh1, H1_OFF, C1_OFF);
        grid_bar();
        // phase 7: gates2 = [h1new|h2prev] @ G2T   (K=2048, 4-way split)
        gemm64(G2T, 4096, H1_OFF, H2_OFF, H2_OFF, 512, G2_OFF, r >> 2, r & 3, shA, shW);
        grid_bar();
        // phase 8: LSTM cell 2 (writes new h2)
        cell_dev(G2_OFF, b_ih2, b_hh2, H2_OFF, C2_OFF);
        grid_bar();
    }
    head_dev(w_out, b_out, out, SDIM - 1);
}

// ---------------- host ----------------
extern "C" void kernel_launch(void* const* d_in, const int* in_sizes, int n_in,
                              void* d_out, int out_size) {
    const float* cnn    = (const float*)d_in[0];
    const float* w_qkv  = (const float*)d_in[1];
    const float* b_qkv  = (const float*)d_in[2];
    const float* w_o    = (const float*)d_in[3];
    const float* b_o    = (const float*)d_in[4];
    const float* w_ih1  = (const float*)d_in[5];
    const float* w_hh1  = (const float*)d_in[6];
    const float* b_ih1  = (const float*)d_in[7];
    const float* b_hh1  = (const float*)d_in[8];
    const float* w_ih2  = (const float*)d_in[9];
    const float* w_hh2  = (const float*)d_in[10];
    const float* b_ih2  = (const float*)d_in[11];
    const float* b_hh2  = (const float*)d_in[12];
    const float* w_out  = (const float*)d_in[13];
    const float* b_out  = (const float*)d_in[14];
    float* out = (float*)d_out;

    dim3 tb(32, 8);
    // one-time k-major weight transposes into scratch
    trans_tiled<<<dim3(32, 32),  tb>>>(w_qkv, 1024, QT_OFF,  1024, 0);     // w_q rows 0..1023
    trans_tiled<<<dim3(32, 32),  tb>>>(w_o,   1024, OT_OFF,  1024, 0);
    trans_tiled<<<dim3(64, 128), tb>>>(w_ih1, 2048, G1T_OFF, 4096, 0);     // k 0..2047 = [h2|ctx]
    trans_tiled<<<dim3(32, 128), tb>>>(w_hh1, 1024, G1T_OFF, 4096, 2048);  // k 2048..3071 = h1
    trans_tiled<<<dim3(32, 128), tb>>>(w_ih2, 1024, G2T_OFF, 4096, 0);     // k 0..1023 = h1new
    trans_tiled<<<dim3(32, 128), tb>>>(w_hh2, 1024, G2T_OFF, 4096, 1024);  // k 1024..2047 = h2prev

    // K/V projections (fp32) into attention-friendly layouts
    gemm_kv<<<dim3(32, 256), 256>>>(cnn, w_qkv, b_qkv);

    // entire recurrence in one persistent kernel (256 co-resident CTAs, 2/SM)
    main_kernel<<<NCTA, NTHR>>>(b_qkv, b_o,
                                b_ih1, b_hh1, b_ih2, b_hh2,
                                w_out, b_out, out);
}